// round 6
// baseline (speedup 1.0000x reference)
#include <cuda_runtime.h>
#include <math.h>

// Problem dims
#define NB 1024   // batch
#define NL 128    // sequence length
#define NH 256    // hidden
#define NI 32     // latent per step
#define NZ 128    // input size

// Persistent decode tiling
#define RB 64     // rows per block
#define HB 32     // hidden cols per block
#define KP 258    // padded k stride (even, breaks 32-bank periodicity)

// ---------------- device scratch (no allocations allowed) ----------------
__device__ float g_t1[NB * 512];
__device__ float g_t2[NB * 512];
__device__ float g_h[NB * NH];
__device__ float g_c0[NB * NH];
__device__ float g_x0[NB * NH];
__device__ float g_cA[NB * NH];
__device__ float g_Wsum[4 * NH * NH];        // rWih + rWhh  [1024,256]
__device__ float g_rb[4 * NH];               // rbih + rbhh
__device__ float g_pb[4 * NI];               // pbih + pbhh
__device__ float g_outs[NL * NB * NH];       // decode LSTM outputs [L,B,H]
__device__ float g_X[NL * NB * 4 * NI];      // outs @ pWih^T + pb  [L,B,128]
__device__ int g_cnt;                        // grid barrier arrive counter
__device__ int g_gen;                        // grid barrier generation

// ---------------- helpers ----------------
__device__ __forceinline__ float sigf(float x) { return 1.0f / (1.0f + __expf(-x)); }
__device__ __forceinline__ float tanhfast(float x) {
    // tanh(x) = 2*sigmoid(2x) - 1
    return fmaf(2.0f, 1.0f / (1.0f + __expf(-2.0f * x)), -1.0f);
}

typedef unsigned long long ull;
__device__ __forceinline__ ull pack2(float lo, float hi) {
    ull r; asm("mov.b64 %0, {%1, %2};" : "=l"(r) : "f"(lo), "f"(hi)); return r;
}
__device__ __forceinline__ float2 unpack2(ull v) {
    float2 r; asm("mov.b64 {%0, %1}, %2;" : "=f"(r.x), "=f"(r.y) : "l"(v)); return r;
}
__device__ __forceinline__ float foldf(ull v) { float2 t = unpack2(v); return t.x + t.y; }
__device__ __forceinline__ void fma2(ull& d, ull a, ull b) {
    asm("fma.rn.f32x2 %0, %1, %2, %0;" : "+l"(d) : "l"(a), "l"(b));
}

// ---------------- prep: Wsum = rWih + rWhh, combined biases, barrier reset ----------------
__global__ void prep_kernel(const float* __restrict__ rWih, const float* __restrict__ rWhh,
                            const float* __restrict__ rbih, const float* __restrict__ rbhh,
                            const float* __restrict__ pbih, const float* __restrict__ pbhh) {
    int i = blockIdx.x * blockDim.x + threadIdx.x;
    int stride = gridDim.x * blockDim.x;
    for (int j = i; j < 4 * NH * NH; j += stride) g_Wsum[j] = rWih[j] + rWhh[j];
    if (i < 4 * NH) g_rb[i] = rbih[i] + rbhh[i];
    if (i < 4 * NI) g_pb[i] = pbih[i] + pbhh[i];
    if (i == 0) { g_cnt = 0; g_gen = 0; }
}

// ---------------- generic GEMM: C = act(A @ W^T + bias) ----------------
#define GM 64
#define GN 64
#define GK 16
__global__ void __launch_bounds__(256, 4)
gemm_bias_act(const float* __restrict__ A, const float* __restrict__ W,
              const float* __restrict__ bias, float* __restrict__ C,
              int M, int N, int K, int act) {
    __shared__ __align__(16) float As[GK][GM + 4];
    __shared__ __align__(16) float Bs[GK][GN + 4];
    const int tid = threadIdx.x;              // 256 threads
    const int tc = tid & 15, tr = tid >> 4;   // 16x16
    const int r0 = blockIdx.x * GM;
    const int c0 = blockIdx.y * GN;

    float acc[4][4];
#pragma unroll
    for (int i = 0; i < 4; ++i)
#pragma unroll
        for (int j = 0; j < 4; ++j) acc[i][j] = 0.0f;

    for (int kc = 0; kc < K; kc += GK) {
#pragma unroll
        for (int it = 0; it < 4; ++it) {
            int idx = tid + it * 256;
            int kl = idx & 15, row = idx >> 4;
            As[kl][row] = A[(size_t)(r0 + row) * K + kc + kl];
        }
#pragma unroll
        for (int it = 0; it < 4; ++it) {
            int idx = tid + it * 256;
            int kl = idx & 15, col = idx >> 4;
            Bs[kl][col] = W[(size_t)(c0 + col) * K + kc + kl];
        }
        __syncthreads();
#pragma unroll
        for (int kk = 0; kk < GK; ++kk) {
            float4 a4 = *(const float4*)&As[kk][tr * 4];
            float4 b4 = *(const float4*)&Bs[kk][tc * 4];
            float av[4] = {a4.x, a4.y, a4.z, a4.w};
            float bv[4] = {b4.x, b4.y, b4.z, b4.w};
#pragma unroll
            for (int i = 0; i < 4; ++i)
#pragma unroll
                for (int j = 0; j < 4; ++j) acc[i][j] = fmaf(av[i], bv[j], acc[i][j]);
        }
        __syncthreads();
    }

    float bv[4];
#pragma unroll
    for (int j = 0; j < 4; ++j) bv[j] = bias[c0 + tc * 4 + j];
#pragma unroll
    for (int i = 0; i < 4; ++i) {
        float4 o; float* po = (float*)&o;
#pragma unroll
        for (int j = 0; j < 4; ++j) {
            float v = acc[i][j] + bv[j];
            if (act) v = (v >= 0.0f) ? v : 0.2f * v;
            po[j] = v;
        }
        *(float4*)&C[(size_t)(r0 + tr * 4 + i) * N + c0 + tc * 4] = o;
    }
}

// ---------------- step-0 LSTM kernel (two GEMM passes: x0@rWih + h@rWhh) ----------------
#define DBM 64
#define DBH 32
#define DKC 32
__global__ void __launch_bounds__(128, 1)
lstm_step_kernel(const float* __restrict__ A1, const float* __restrict__ W1,
                 const float* __restrict__ A2, const float* __restrict__ W2,
                 const float* __restrict__ bias, const float* __restrict__ c_prev,
                 float* __restrict__ h_out, float* __restrict__ c_out) {
    __shared__ __align__(16) float As[DKC][DBM + 2];
    __shared__ __align__(16) float Ws[4][DBH][DKC + 1];
    const int tid = threadIdx.x;            // 128 threads
    const int tc = tid & 15;
    const int tr = tid >> 4;
    const int r0 = blockIdx.x * DBM;
    const int c0 = blockIdx.y * DBH;

    float accs[4][2][8];
#pragma unroll
    for (int g = 0; g < 4; ++g)
#pragma unroll
        for (int cc = 0; cc < 2; ++cc)
#pragma unroll
            for (int p = 0; p < 8; ++p) accs[g][cc][p] = 0.0f;

    for (int pass = 0; pass < 2; ++pass) {
        const float* A = pass ? A2 : A1;
        const float* W = pass ? W2 : W1;
        for (int kc = 0; kc < NH; kc += DKC) {
#pragma unroll
            for (int it = 0; it < 16; ++it) {
                int idx = tid + it * 128;
                int kl = idx & 31, row = idx >> 5;
                As[kl][row] = A[(size_t)(r0 + row) * NH + kc + kl];
            }
#pragma unroll
            for (int it = 0; it < 32; ++it) {
                int idx = tid + it * 128;
                int kl = idx & 31, hh = (idx >> 5) & 31, gg = idx >> 10;
                Ws[gg][hh][kl] = W[(size_t)(gg * NH + c0 + hh) * NH + kc + kl];
            }
            __syncthreads();
#pragma unroll 4
            for (int kk = 0; kk < DKC; ++kk) {
                float a[8];
#pragma unroll
                for (int p = 0; p < 8; ++p) a[p] = As[kk][tr * 8 + p];
#pragma unroll
                for (int g = 0; g < 4; ++g)
#pragma unroll
                    for (int cc = 0; cc < 2; ++cc) {
                        float w = Ws[g][tc * 2 + cc][kk];
#pragma unroll
                        for (int p = 0; p < 8; ++p) accs[g][cc][p] = fmaf(a[p], w, accs[g][cc][p]);
                    }
            }
            __syncthreads();
        }
    }

#pragma unroll
    for (int cc = 0; cc < 2; ++cc) {
        int hcol = c0 + tc * 2 + cc;
        float bI = bias[0 * NH + hcol], bF = bias[1 * NH + hcol];
        float bg = bias[2 * NH + hcol], bO = bias[3 * NH + hcol];
#pragma unroll
        for (int p = 0; p < 8; ++p) {
            int row = r0 + tr * 8 + p;
            float iv = accs[0][cc][p] + bI, fv = accs[1][cc][p] + bF;
            float gv = accs[2][cc][p] + bg, ov = accs[3][cc][p] + bO;
            float cp = c_prev[(size_t)row * NH + hcol];
            float cn = sigf(fv) * cp + sigf(iv) * tanhfast(gv);
            float hn = sigf(ov) * tanhfast(cn);
            c_out[(size_t)row * NH + hcol] = cn;
            h_out[(size_t)row * NH + hcol] = hn;
        }
    }
}

// ---------------- persistent decode kernel: steps 1..127 + fused X projection ----------------
// grid (16 row-blocks, 8 col-blocks) = 128 blocks, 256 threads, ~210KB dyn smem.
// Block (br,bc): rows r0..r0+64, gate-hcols c0..c0+32, X-cols nc0..nc0+16.
// W_sum slice + pWih slice resident in smem; c state resident in registers.
// Grid barrier between steps (all 128 blocks co-resident: 1 block/SM, 128 <= 148 SMs).
#define SMEM_FLOATS (4 * HB * KP + RB * KP + 16 * KP)
__global__ void __launch_bounds__(256, 1)
persistent_decode(float* __restrict__ outs, const float* __restrict__ Wsum,
                  const float* __restrict__ pWih, float* __restrict__ X) {
    extern __shared__ float sm[];
    float* sW  = sm;                       // [4][HB][KP]
    float* sA  = sm + 4 * HB * KP;         // [RB][KP]
    float* sPW = sA + RB * KP;             // [16][KP]

    const int tid = threadIdx.x;           // 256
    const int tc = tid & 15;               // hcol-pair / X-col
    const int tr = tid >> 4;               // row group (4 rows)
    const int r0 = blockIdx.x * RB;
    const int c0 = blockIdx.y * HB;
    const int nc0 = blockIdx.y * 16;

    // ---- one-time loads: W slice (4x32x256), pW slice (16x256) ----
    for (int v = tid; v < 4 * HB * 64; v += 256) {
        int kq = v & 63, h = (v >> 6) & 31, g = v >> 11;
        float4 w = __ldcg((const float4*)&Wsum[((size_t)(g * NH + c0 + h)) * NH + kq * 4]);
        float* d = &sW[(g * HB + h) * KP + kq * 4];
        ((float2*)d)[0] = make_float2(w.x, w.y);
        ((float2*)d)[1] = make_float2(w.z, w.w);
    }
    for (int v = tid; v < 16 * 64; v += 256) {
        int kq = v & 63, c = v >> 6;
        float4 w = __ldcg((const float4*)&pWih[(size_t)(nc0 + c) * NH + kq * 4]);
        float* d = &sPW[c * KP + kq * 4];
        ((float2*)d)[0] = make_float2(w.x, w.y);
        ((float2*)d)[1] = make_float2(w.z, w.w);
    }

    // ---- register-resident state & biases ----
    float bG[4][2];
#pragma unroll
    for (int g = 0; g < 4; ++g)
#pragma unroll
        for (int c = 0; c < 2; ++c) bG[g][c] = g_rb[g * NH + c0 + tc * 2 + c];
    const float pbv = g_pb[nc0 + tc];

    float creg[4][2];
#pragma unroll
    for (int i = 0; i < 4; ++i)
#pragma unroll
        for (int c = 0; c < 2; ++c)
            creg[i][c] = g_cA[(size_t)(r0 + tr * 4 + i) * NH + c0 + tc * 2 + c];

    const float* sWg = &sW[(tc * 2) * KP];     // per-thread W base (g stride = HB*KP)
    const float* sAg = &sA[(tr * 4) * KP];     // per-thread A base
    const float* sPg = &sPW[tc * KP];

    for (int s = 1; s < NL; ++s) {
        // load A tile = outs[s-1] rows [r0, r0+64)
        const float* Aptr = outs + (size_t)(s - 1) * NB * NH;
        for (int v = tid; v < RB * 64; v += 256) {
            int kq = v & 63, row = v >> 6;
            float4 w = __ldcg((const float4*)&Aptr[(size_t)(r0 + row) * NH + kq * 4]);
            float* d = &sA[row * KP + kq * 4];
            ((float2*)d)[0] = make_float2(w.x, w.y);
            ((float2*)d)[1] = make_float2(w.z, w.w);
        }
        __syncthreads();

        // accumulators: split-K packed pairs; fold = lo+hi at end, so init (bias, 0)
        ull acc[4][4][2];
#pragma unroll
        for (int g = 0; g < 4; ++g)
#pragma unroll
            for (int i = 0; i < 4; ++i)
#pragma unroll
                for (int c = 0; c < 2; ++c) acc[g][i][c] = pack2(bG[g][c], 0.0f);
        ull accp[4];
#pragma unroll
        for (int i = 0; i < 4; ++i) accp[i] = pack2(pbv, 0.0f);

#pragma unroll 2
        for (int kk = 0; kk < NH / 2; ++kk) {
            ull a[4];
#pragma unroll
            for (int i = 0; i < 4; ++i)
                a[i] = *(const ull*)&sAg[i * KP + 2 * kk];
            // fused projection (X[s-1]) — reuses a[]
            {
                ull wp = *(const ull*)&sPg[2 * kk];
#pragma unroll
                for (int i = 0; i < 4; ++i) fma2(accp[i], a[i], wp);
            }
            // gates
#pragma unroll
            for (int g = 0; g < 4; ++g)
#pragma unroll
                for (int c = 0; c < 2; ++c) {
                    ull w = *(const ull*)&sWg[(g * HB + c) * KP + 2 * kk];
#pragma unroll
                    for (int i = 0; i < 4; ++i) fma2(acc[g][i][c], a[i], w);
                }
        }

        // write X[s-1]
#pragma unroll
        for (int i = 0; i < 4; ++i)
            X[((size_t)(s - 1) * NB + r0 + tr * 4 + i) * (4 * NI) + nc0 + tc] = foldf(accp[i]);

        // LSTM cell + write h -> outs[s]
        float* Hout = outs + (size_t)s * NB * NH;
#pragma unroll
        for (int i = 0; i < 4; ++i) {
            int row = r0 + tr * 4 + i;
#pragma unroll
            for (int c = 0; c < 2; ++c) {
                float iv = foldf(acc[0][i][c]);
                float fv = foldf(acc[1][i][c]);
                float gv = foldf(acc[2][i][c]);
                float ov = foldf(acc[3][i][c]);
                float cn = sigf(fv) * creg[i][c] + sigf(iv) * tanhfast(gv);
                creg[i][c] = cn;
                Hout[(size_t)row * NH + c0 + tc * 2 + c] = sigf(ov) * tanhfast(cn);
            }
        }

        // ---- grid barrier ----
        __threadfence();
        __syncthreads();
        if (tid == 0) {
            int t = atomicAdd(&g_cnt, 1);
            if (t == gridDim.x * gridDim.y - 1) {
                atomicExch(&g_cnt, 0);
                __threadfence();
                atomicExch(&g_gen, s);
            } else {
                while (((volatile int*)&g_gen)[0] < s) __nanosleep(64);
                __threadfence();
            }
        }
        __syncthreads();
    }

    // ---- final projection X[127] from outs[127] (visible via last barrier) ----
    {
        const float* Aptr = outs + (size_t)(NL - 1) * NB * NH;
        for (int v = tid; v < RB * 64; v += 256) {
            int kq = v & 63, row = v >> 6;
            float4 w = __ldcg((const float4*)&Aptr[(size_t)(r0 + row) * NH + kq * 4]);
            float* d = &sA[row * KP + kq * 4];
            ((float2*)d)[0] = make_float2(w.x, w.y);
            ((float2*)d)[1] = make_float2(w.z, w.w);
        }
        __syncthreads();
        ull accp[4];
#pragma unroll
        for (int i = 0; i < 4; ++i) accp[i] = pack2(pbv, 0.0f);
#pragma unroll 4
        for (int kk = 0; kk < NH / 2; ++kk) {
            ull wp = *(const ull*)&sPg[2 * kk];
#pragma unroll
            for (int i = 0; i < 4; ++i) {
                ull a = *(const ull*)&sAg[i * KP + 2 * kk];
                fma2(accp[i], a, wp);
            }
        }
#pragma unroll
        for (int i = 0; i < 4; ++i)
            X[((size_t)(NL - 1) * NB + r0 + tr * 4 + i) * (4 * NI) + nc0 + tc] = foldf(accp[i]);
    }
}

// ---------------- persistent predictor LSTM + softmax/sigmoid epilogue ----------------
__global__ void __launch_bounds__(256, 4)
pred_kernel(const float* __restrict__ pWhh, float* __restrict__ out) {
    __shared__ float pWt[NI][4 * NI + 4];
    const int tid = threadIdx.x;            // 256 = 8 warps
    const int lane = tid & 31;
    const int wid = tid >> 5;
    for (int idx = tid; idx < 4 * NI * NI; idx += 256) {
        int k = idx & 31, j = idx >> 5;
        pWt[k][j] = pWhh[j * NI + k];
    }
    __syncthreads();

    const int b = blockIdx.x * 8 + wid;
    float ph = 0.0f, pc = 0.0f;

    for (int s = 0; s < NL; ++s) {
        const size_t base = ((size_t)s * NB + b) * (4 * NI);
        float gv[4];
#pragma unroll
        for (int g = 0; g < 4; ++g) gv[g] = g_X[base + g * NI + lane];
#pragma unroll 8
        for (int k = 0; k < NI; ++k) {
            float p = __shfl_sync(0xffffffffu, ph, k);
#pragma unroll
            for (int g = 0; g < 4; ++g) gv[g] = fmaf(p, pWt[k][g * NI + lane], gv[g]);
        }
        pc = sigf(gv[1]) * pc + sigf(gv[0]) * tanhfast(gv[2]);
        ph = sigf(gv[3]) * tanhfast(pc);

        float v = (lane < 31) ? ph : -1e30f;
#pragma unroll
        for (int off = 16; off > 0; off >>= 1) v = fmaxf(v, __shfl_xor_sync(0xffffffffu, v, off));
        float e = (lane < 31) ? __expf(ph - v) : 0.0f;
        float ssum = e;
#pragma unroll
        for (int off = 16; off > 0; off >>= 1) ssum += __shfl_xor_sync(0xffffffffu, ssum, off);
        float o = (lane < 31) ? (e / ssum) : sigf(ph);
        out[((size_t)b * NL + s) * NI + lane] = o;
    }
}

// ---------------- host launch ----------------
extern "C" void kernel_launch(void* const* d_in, const int* in_sizes, int n_in,
                              void* d_out, int out_size) {
    const float* x    = (const float*)d_in[0];
    const float* W1   = (const float*)d_in[1];  const float* b1  = (const float*)d_in[2];
    const float* W2   = (const float*)d_in[3];  const float* b2  = (const float*)d_in[4];
    const float* W3   = (const float*)d_in[5];  const float* b3  = (const float*)d_in[6];
    const float* Wh1  = (const float*)d_in[7];  const float* bh1 = (const float*)d_in[8];
    const float* Wh2  = (const float*)d_in[9];  const float* bh2 = (const float*)d_in[10];
    const float* Wc1  = (const float*)d_in[11]; const float* bc1 = (const float*)d_in[12];
    const float* Wc2  = (const float*)d_in[13]; const float* bc2 = (const float*)d_in[14];
    const float* Wx1  = (const float*)d_in[15]; const float* bx1 = (const float*)d_in[16];
    const float* Wx2  = (const float*)d_in[17]; const float* bx2 = (const float*)d_in[18];
    const float* rWih = (const float*)d_in[19]; const float* rWhh = (const float*)d_in[20];
    const float* rbih = (const float*)d_in[21]; const float* rbhh = (const float*)d_in[22];
    const float* pWih = (const float*)d_in[23]; const float* pWhh = (const float*)d_in[24];
    const float* pbih = (const float*)d_in[25]; const float* pbhh = (const float*)d_in[26];

    void* p;
    cudaGetSymbolAddress(&p, g_t1);   float* t1   = (float*)p;
    cudaGetSymbolAddress(&p, g_t2);   float* t2   = (float*)p;
    cudaGetSymbolAddress(&p, g_h);    float* hbuf = (float*)p;
    cudaGetSymbolAddress(&p, g_c0);   float* c0b  = (float*)p;
    cudaGetSymbolAddress(&p, g_x0);   float* x0b  = (float*)p;
    cudaGetSymbolAddress(&p, g_Wsum); float* wsum = (float*)p;
    cudaGetSymbolAddress(&p, g_rb);   float* rb   = (float*)p;
    cudaGetSymbolAddress(&p, g_outs); float* outs = (float*)p;
    cudaGetSymbolAddress(&p, g_X);    float* Xb   = (float*)p;
    cudaGetSymbolAddress(&p, g_cA);   float* cA   = (float*)p;

    // Host-side attribute set; not a stream op, legal under capture; no static guards.
    const int smem_bytes = SMEM_FLOATS * (int)sizeof(float);   // 214,656 B
    cudaFuncSetAttribute(persistent_decode,
                         cudaFuncAttributeMaxDynamicSharedMemorySize, smem_bytes);

    prep_kernel<<<256, 256>>>(rWih, rWhh, rbih, rbhh, pbih, pbhh);

    // Front MLP: 3x linear+leaky
    gemm_bias_act<<<dim3(NB / GM, 512 / GN), 256>>>(x,  W1, b1, t1, NB, 512, NZ, 1);
    gemm_bias_act<<<dim3(NB / GM, 512 / GN), 256>>>(t1, W2, b2, t2, NB, 512, 512, 1);
    gemm_bias_act<<<dim3(NB / GM, 512 / GN), 256>>>(t2, W3, b3, t1, NB, 512, 512, 1);
    // Heads: h, c, x0
    gemm_bias_act<<<dim3(NB / GM, 512 / GN), 256>>>(t1, Wh1, bh1, t2, NB, 512, 512, 1);
    gemm_bias_act<<<dim3(NB / GM, NH / GN),  256>>>(t2, Wh2, bh2, hbuf, NB, NH, 512, 0);
    gemm_bias_act<<<dim3(NB / GM, 512 / GN), 256>>>(t1, Wc1, bc1, t2, NB, 512, 512, 1);
    gemm_bias_act<<<dim3(NB / GM, NH / GN),  256>>>(t2, Wc2, bc2, c0b, NB, NH, 512, 0);
    gemm_bias_act<<<dim3(NB / GM, 512 / GN), 256>>>(t1, Wx1, bx1, t2, NB, 512, 512, 1);
    gemm_bias_act<<<dim3(NB / GM, NH / GN),  256>>>(t2, Wx2, bx2, x0b, NB, NH, 512, 0);

    // Decode step 0: gates = x0@rWih^T + h@rWhh^T + rb, c from c0 -> outs[0], cA
    lstm_step_kernel<<<dim3(NB / DBM, NH / DBH), 128>>>(x0b, rWih, hbuf, rWhh, rb, c0b,
                                                        outs, cA);

    // Steps 1..127 + all X projections in ONE persistent kernel
    persistent_decode<<<dim3(NB / RB, NH / HB), 256, smem_bytes>>>(outs, wsum, pWih, Xb);

    // Predictor LSTM + softmax/sigmoid epilogue
    pred_kernel<<<NB / 8, 256>>>(pWhh, (float*)d_out);
}